// round 15
// baseline (speedup 1.0000x reference)
#include <cuda_runtime.h>
#include <cuda_bf16.h>
#include <stdint.h>
#include <math.h>

typedef unsigned short u16;
typedef unsigned int   u32;
typedef unsigned long long u64;

#define Bsz  64
#define Dd   256
#define NPp  1024
#define NTOK 1025
#define NTOKP 1032         /* 1025 padded to mult of 8 -> 16B-aligned rows */
#define NTOKH 513          /* quadrant rows 0..512 */
#define KFOLD 513          /* folded token-K */
#define LDV  520           /* 513 padded to mult of 8 */
#define HIDN 1024
#define NL   6
#define NCls 1000
#define ROWS 65600
#define KIN  768
#define KMP  1088          /* 1025 padded to mult of 64 */
#define EPSV 1e-5f

/* ---------------- device-global scratch ---------------- */
__device__ float g_t   [(size_t)ROWS*Dd];
__device__ float g_pool[Bsz*Dd];
__device__ float g_t1f [(size_t)Bsz*Dd*NTOKP];    /* stage-1 fp32 out (u1;u2) */
__device__ float g_ycq [(size_t)Bsz*NTOKH*136];   /* cos quadrant (ld 136) */
__device__ float g_ysq [(size_t)Bsz*512*128];     /* sin quadrant 512x127 (ld 128) */
__device__ __align__(16) u16 g_vh  [(size_t)Bsz*Dd*LDV];   /* folded stage-2 B, hi */
__device__ __align__(16) u16 g_vl  [(size_t)Bsz*Dd*LDV];   /* folded stage-2 B, lo */
__device__ __align__(16) u16 g_colh[(size_t)Bsz*NPp*KIN];
__device__ __align__(16) u16 g_coll[(size_t)Bsz*NPp*KIN];
__device__ __align__(16) u16 g_hh  [(size_t)ROWS*Dd];
__device__ __align__(16) u16 g_hidh[(size_t)ROWS*HIDN];
__device__ __align__(16) u16 g_cmh [(size_t)NTOKH*KMP];
__device__ __align__(16) u16 g_cml [(size_t)NTOKH*KMP];
__device__ __align__(16) u16 g_smh [(size_t)NTOKH*KMP];
__device__ __align__(16) u16 g_sml [(size_t)NTOKH*KMP];
__device__ __align__(16) u16 g_stkh[Dd*Dd], g_stkl[Dd*Dd];  /* stacked [CN0..128;SN1..127] */
__device__ __align__(16) u16 g_w1h [NL*Dd*HIDN];
__device__ __align__(16) u16 g_w2h [NL*Dd*HIDN];
__device__ __align__(16) u16 g_cwh [Dd*KIN];

/* ---------------- helpers ---------------- */
__device__ __forceinline__ u32 s2u(const void* p){
    u32 a; asm("{ .reg .u64 t; cvta.to.shared.u64 t, %1; cvt.u32.u64 %0, t; }" : "=r"(a) : "l"(p));
    return a;
}
__device__ __forceinline__ void split3(float v, u16& hu, u16& lu){
    __nv_bfloat16 h = __float2bfloat16(v);
    hu = __bfloat16_as_ushort(h);
    lu = __bfloat16_as_ushort(__float2bfloat16(v - __bfloat162float(h)));
}
__device__ __forceinline__ float b2f(u16 u){
    return __bfloat162float(__ushort_as_bfloat16(u));
}
__device__ __forceinline__ u16 f2b(float v){
    return __bfloat16_as_ushort(__float2bfloat16(v));
}

#define CPA(s, g, n) asm volatile("cp.async.ca.shared.global [%0], [%1], 16, %2;" :: "r"(s), "l"(g), "r"(n) : "memory")
#define CP_COMMIT()  asm volatile("cp.async.commit_group;" ::: "memory")

#define LDSM4(r, a) asm volatile("ldmatrix.sync.aligned.m8n8.x4.shared.b16 {%0,%1,%2,%3}, [%4];" \
    : "=r"((r)[0]), "=r"((r)[1]), "=r"((r)[2]), "=r"((r)[3]) : "r"(a))

#define MMA16816(d, a, b0v, b1v)                                               \
    asm volatile("mma.sync.aligned.m16n8k16.row.col.f32.bf16.bf16.f32 "        \
        "{%0,%1,%2,%3},{%4,%5,%6,%7},{%8,%9},{%0,%1,%2,%3};"                   \
        : "+f"((d)[0]), "+f"((d)[1]), "+f"((d)[2]), "+f"((d)[3])               \
        : "r"((a)[0]), "r"((a)[1]), "r"((a)[2]), "r"((a)[3]), "r"(b0v), "r"(b1v))

/* ---------------- stage one 128x32 A-tile + 128x32 B-tile into smem -------- */
__device__ __forceinline__ void stage_tile(u32 sa, u32 sbm,
    const u16* __restrict__ As, const u16* __restrict__ Bs,
    int lda, int ldb, int M, int N, int K, int m0, int n0, int k0, int tid)
{
#pragma unroll
    for (int i = 0; i < 2; i++) {
        int slot = tid + i * 256;
        int r = slot >> 2, c = slot & 3;
        int kk = k0 + c * 8;
        int gm = m0 + r;
        int bytes = 0; size_t off = 0;
        if (gm < M && kk < K) { bytes = (K - kk >= 8) ? 16 : (K - kk) * 2; off = (size_t)gm * lda + kk; }
        CPA(sa + r * 80 + c * 16, As + off, bytes);
    }
#pragma unroll
    for (int i = 0; i < 2; i++) {
        int slot = tid + i * 256;
        int r = slot >> 2, c = slot & 3;
        int kk = k0 + c * 8;
        int gn = n0 + r;
        int bytes = 0; size_t off = 0;
        if (gn < N && kk < K) { bytes = (K - kk >= 8) ? 16 : (K - kk) * 2; off = (size_t)gn * ldb + kk; }
        CPA(sbm + r * 80 + c * 16, Bs + off, bytes);
    }
    CP_COMMIT();
}

/* ---------------- shared GEMM body: D(tile at m0,n0) = A @ B^T, bf16 split --
   npass=3: Ah.Bh + Al.Bh + Ah.Bl ; npass=2: Ah.Bh + Al.Bh ; npass=1: Ah.Bh
   EPI: 1 bias+leaky+hi-store   3 f32 C += acc + bias
        5 f32 C = acc           6 f32 C = acc + bias + pos(row gm+1) */
template<int EPI>
__device__ __forceinline__ void mm_body(
    u32 sa0, u32 sa1, u32 sb0, u32 sb1,
    const u16* __restrict__ Ah, const u16* __restrict__ Al, int lda,
    const u16* __restrict__ Bh, const u16* __restrict__ Bl, int ldb,
    int M, int N, int K, int m0, int n0,
    const float* __restrict__ bias, const float* __restrict__ pos,
    float* C, u16* Ch, int ldc, int npass)
{
    const int tid = threadIdx.x, lane = tid & 31, wid = tid >> 5;
    const int wm = wid & 3, wn = wid >> 2;

    const u16* Ap[3] = { Ah, Al, Ah };
    const u16* Bp[3] = { Bh, Bh, Bl };
    const int nk = (K + 31) >> 5, total = npass * nk;

    float acc[2][8][4];
#pragma unroll
    for (int mi = 0; mi < 2; mi++)
#pragma unroll
        for (int n8 = 0; n8 < 8; n8++)
#pragma unroll
            for (int q = 0; q < 4; q++) acc[mi][n8][q] = 0.f;

    stage_tile(sa0, sb0, Ap[0], Bp[0], lda, ldb, M, N, K, m0, n0, 0, tid);

    for (int it = 0; it < total; it++) {
        if (it + 1 < total) {
            int p = (it + 1) / nk, kc = (it + 1) - p * nk;
            stage_tile(((it + 1) & 1) ? sa1 : sa0, ((it + 1) & 1) ? sb1 : sb0,
                       Ap[p], Bp[p], lda, ldb, M, N, K, m0, n0, kc * 32, tid);
            asm volatile("cp.async.wait_group 1;" ::: "memory");
        } else {
            asm volatile("cp.async.wait_group 0;" ::: "memory");
        }
        __syncthreads();
        u32 sa = (it & 1) ? sa1 : sa0, smb = (it & 1) ? sb1 : sb0;
#pragma unroll
        for (int kk = 0; kk < 32; kk += 16) {
            u32 a[2][4], b[4][4];
#pragma unroll
            for (int mi = 0; mi < 2; mi++)
                LDSM4(a[mi], sa + (u32)((wm * 32 + mi * 16 + (lane & 15)) * 80
                                        + (kk + (lane >> 4) * 8) * 2));
#pragma unroll
            for (int nj = 0; nj < 4; nj++)
                LDSM4(b[nj], smb + (u32)((wn * 64 + nj * 16 + ((lane >> 4) << 3) + (lane & 7)) * 80
                                         + (kk + ((lane >> 3) & 1) * 8) * 2));
#pragma unroll
            for (int mi = 0; mi < 2; mi++)
#pragma unroll
                for (int n8 = 0; n8 < 8; n8++)
                    MMA16816(acc[mi][n8], a[mi], b[n8 >> 1][(n8 & 1) * 2], b[n8 >> 1][(n8 & 1) * 2 + 1]);
        }
        __syncthreads();
    }

    /* epilogue from register fragments */
#pragma unroll
    for (int mi = 0; mi < 2; mi++) {
        int rbase = m0 + wm * 32 + mi * 16 + (lane >> 2);
#pragma unroll
        for (int half = 0; half < 2; half++) {
            int gm = rbase + half * 8;
            if (gm >= M) continue;
#pragma unroll
            for (int n8 = 0; n8 < 8; n8++) {
                int gn = n0 + wn * 64 + n8 * 8 + (lane & 3) * 2;
                if (gn >= N) continue;
                float v0 = acc[mi][n8][half * 2], v1 = acc[mi][n8][half * 2 + 1];
                size_t off = (size_t)gm * ldc + gn;
                if (EPI == 1) {
                    v0 += bias[gn];     v0 = v0 > 0.f ? v0 : 0.01f * v0;
                    v1 += bias[gn + 1]; v1 = v1 > 0.f ? v1 : 0.01f * v1;
                    u32 hp = (u32)f2b(v0) | ((u32)f2b(v1) << 16);
                    *(u32*)(Ch + off) = hp;
                } else if (EPI == 5) {
                    *(float2*)(C + off) = make_float2(v0, v1);
                } else if (EPI == 6) {
                    size_t po = (size_t)(gm + 1) * Dd + gn;
                    *(float2*)(C + off) = make_float2(v0 + bias[gn] + pos[po],
                                                      v1 + bias[gn + 1] + pos[po + 1]);
                } else {            /* EPI == 3 */
                    float2 c = *(const float2*)(C + off);
                    c.x += v0 + bias[gn];
                    c.y += v1 + bias[gn + 1];
                    *(float2*)(C + off) = c;
                }
            }
        }
    }
}

/* ---------------- generic single GEMM kernel ---------------- */
template<int EPI>
__global__ __launch_bounds__(256, 2)
void mmg(const u16* __restrict__ Ah, const u16* __restrict__ Al, int lda, long long sA,
         const u16* __restrict__ Bh, const u16* __restrict__ Bl, int ldb, long long sB,
         int M, int N, int K, const float* __restrict__ bias, const float* __restrict__ pos,
         float* C, u16* Ch, int ldc, long long sC, int npass)
{
    __shared__ __align__(16) u16 SA[2][128][40];
    __shared__ __align__(16) u16 SB[2][128][40];
    const int bz = blockIdx.z;
    Ah += bz * sA; Al += bz * sA; Bh += bz * sB;
    if (Bl) Bl += bz * sB;
    if (C)  C  += bz * sC;
    if (Ch) Ch += bz * sC;
    mm_body<EPI>(s2u(&SA[0][0][0]), s2u(&SA[1][0][0]),
                 s2u(&SB[0][0][0]), s2u(&SB[1][0][0]),
                 Ah, Al, lda, Bh, Bl, ldb, M, N, K,
                 blockIdx.y * 128, blockIdx.x * 128, bias, pos, C, Ch, ldc, npass);
}

/* ---------------- dual GEMM + boundary kernel: stage-2 cos/sin/bound -------
   y<4: cos tiles; 4<=y<8: sin tiles; y>=8: boundary warp-dots into ycq. */
__global__ __launch_bounds__(256, 2)
void mmg_dual(const u16* __restrict__ A0h, const u16* __restrict__ A0l,
              const u16* __restrict__ B0h, const u16* __restrict__ B0l,
              float* C0, int ldc0, long long sC0,
              const u16* __restrict__ A1h, const u16* __restrict__ A1l,
              const u16* __restrict__ B1h, const u16* __restrict__ B1l,
              float* C1, int ldc1, long long sC1,
              long long sB)
{
    __shared__ __align__(16) u16 SA[2][128][40];
    __shared__ __align__(16) u16 SB[2][128][40];
    const int bz = blockIdx.z;
    if (blockIdx.y >= 8) {
        /* boundary: fill ycq row m=512 (k 0..128) and column k=128 (m 0..511) */
        int wid = threadIdx.x >> 5, lane = threadIdx.x & 31;
        int gw = (blockIdx.y - 8) * 8 + wid;
        if (gw >= 641) return;
        int m, k;
        if (gw < 512) { m = gw; k = 128; }
        else          { m = 512; k = gw - 512; }
        const u16* cmh = A0h + (size_t)m * KMP;
        const u16* cml = A0l + (size_t)m * KMP;
        const u16* vh  = B0h + bz * sB + (size_t)k * LDV;
        const u16* vl  = B0l + bz * sB + (size_t)k * LDV;
        float s = 0.f;
        for (int j = lane; j < KFOLD; j += 32) {
            float cm = b2f(cmh[j]) + b2f(cml[j]);
            float vv = b2f(vh[j])  + b2f(vl[j]);
            s = fmaf(cm, vv, s);
        }
#pragma unroll
        for (int o = 16; o; o >>= 1) s += __shfl_xor_sync(0xffffffffu, s, o);
        if (!lane) (C0 + bz * sC0)[(size_t)m * ldc0 + k] = s;
        return;
    }
    const int sel = blockIdx.y >= 4;
    const u16 *Ah, *Al, *Bh, *Bl;
    float* C; int ldc, N, m0;
    if (!sel) {
        Ah = A0h; Al = A0l;
        Bh = B0h + bz * sB; Bl = B0l + bz * sB;
        C = C0 + bz * sC0; ldc = ldc0; N = 128;
        m0 = blockIdx.y * 128;
    } else {
        Ah = A1h; Al = A1l;
        Bh = B1h + bz * sB; Bl = B1l + bz * sB;
        C = C1 + bz * sC1; ldc = ldc1; N = 127;
        m0 = (blockIdx.y - 4) * 128;
    }
    mm_body<5>(s2u(&SA[0][0][0]), s2u(&SA[1][0][0]),
               s2u(&SB[0][0][0]), s2u(&SB[1][0][0]),
               Ah, Al, KMP, Bh, Bl, LDV, 512, N, KFOLD,
               m0, 0, nullptr, nullptr, C, nullptr, ldc, 3);
}

/* ---------------- tables ---------------- */
__global__ void dft_split()
{
    long long idx = (long long)blockIdx.x * blockDim.x + threadIdx.x;
    const float TP = 6.283185307179586f;
    if (idx < (long long)NTOKH * KMP) {      /* quadrant rows 0..512 of CM/SM */
        int m = (int)(idx / KMP), j = (int)(idx % KMP);
        float c = 0.f, s = 0.f;
        if (j < NTOK) {
            int r = (int)(((long long)m * j) % NTOK);
            float a = (float)r * (TP / (float)NTOK);
            sincosf(a, &s, &c);
        }
        split3(c, g_cmh[idx], g_cml[idx]);
        split3(s, g_smh[idx], g_sml[idx]);
    }
    if (idx < Dd * Dd) {                     /* stacked dim table */
        int r = (int)(idx >> 8), d = (int)(idx & 255);
        float v;
        if (r < 129) {
            int rr = (r * d) & 255;
            v = cosf((float)rr * (TP / 256.f));
        } else {
            int rr = ((r - 128) * d) & 255;
            v = sinf((float)rr * (TP / 256.f));
        }
        split3(v, g_stkh[idx], g_stkl[idx]);
    }
}
__global__ void im2col_split(const float* __restrict__ x)
{
    long long idx = (long long)blockIdx.x * blockDim.x + threadIdx.x;
    if (idx >= (long long)Bsz * NPp * KIN) return;
    int k = (int)(idx % KIN);
    long long rp = idx / KIN;
    int p = (int)(rp % NPp), b = (int)(rp / NPp);
    int c = k >> 8, py = (k >> 4) & 15, px = k & 15;
    int gh = p >> 5, gw = p & 31;
    float v = x[(((size_t)b * 3 + c) * 512 + gh * 16 + py) * 512 + gw * 16 + px];
    split3(v, g_colh[idx], g_coll[idx]);
}
__global__ void convw_hi(const float* __restrict__ cw)
{
    int idx = blockIdx.x * blockDim.x + threadIdx.x;
    if (idx < Dd * KIN) g_cwh[idx] = f2b(cw[idx]);
}
__global__ void w12t_hi(const float* __restrict__ w1, const float* __restrict__ w2)
{
    int idx = blockIdx.x * blockDim.x + threadIdx.x;
    if (idx >= NL * Dd * HIDN) return;
    int l = idx / (Dd * HIDN), r = idx % (Dd * HIDN);
    int n1 = r / Dd, k1 = r % Dd;
    g_w1h[idx] = f2b(w1[(size_t)l * Dd * HIDN + (size_t)k1 * HIDN + n1]);
    int n2 = r / HIDN, k2 = r % HIDN;
    g_w2h[idx] = f2b(w2[(size_t)l * Dd * HIDN + (size_t)k2 * Dd + n2]);
}
/* cls row: t[b,0,:] = cls + pos[0,:] */
__global__ void cls_row(const float* __restrict__ pos, const float* __restrict__ cls)
{
    int d = threadIdx.x, b = blockIdx.x;
    g_t[(size_t)b * NTOK * Dd + d] = cls[d] + pos[d];
}

/* warp-per-row LN -> bf16 hi only; 8 rows per block, no __syncthreads */
__global__ __launch_bounds__(256)
void ln_split(const float* __restrict__ sc, const float* __restrict__ bi)
{
    int warp = threadIdx.x >> 5, lane = threadIdx.x & 31;
    size_t row = (size_t)blockIdx.x * 8 + warp;
    if (row >= ROWS) return;
    const float4* src = (const float4*)(g_t + row * Dd);
    float4 v0 = src[lane], v1 = src[lane + 32];
    float s = v0.x + v0.y + v0.z + v0.w + v1.x + v1.y + v1.z + v1.w;
#pragma unroll
    for (int o = 16; o; o >>= 1) s += __shfl_xor_sync(0xffffffffu, s, o);
    float m = s * (1.f / Dd);
    float d0[8] = { v0.x - m, v0.y - m, v0.z - m, v0.w - m,
                    v1.x - m, v1.y - m, v1.z - m, v1.w - m };
    float q = 0.f;
#pragma unroll
    for (int i = 0; i < 8; i++) q = fmaf(d0[i], d0[i], q);
#pragma unroll
    for (int o = 16; o; o >>= 1) q += __shfl_xor_sync(0xffffffffu, q, o);
    float inv = rsqrtf(q * (1.f / Dd) + EPSV);
    float4 s0 = ((const float4*)sc)[lane], s1 = ((const float4*)sc)[lane + 32];
    float4 b0 = ((const float4*)bi)[lane], b1 = ((const float4*)bi)[lane + 32];
    float scv[8] = { s0.x, s0.y, s0.z, s0.w, s1.x, s1.y, s1.z, s1.w };
    float biv[8] = { b0.x, b0.y, b0.z, b0.w, b1.x, b1.y, b1.z, b1.w };
    u16 hh[8];
#pragma unroll
    for (int i = 0; i < 8; i++) hh[i] = f2b(d0[i] * inv * scv[i] + biv[i]);
    uint2* dh = (uint2*)(g_hh + row * Dd);
    dh[lane]      = *(uint2*)&hh[0];
    dh[lane + 32] = *(uint2*)&hh[4];
}

/* fused combine_quad + ln2: warp per token row.
   Row m pulls quadrant row m' = min(m, 1025-m); contribution at column k is
   yc(m',kq) +/- ys(m',kq) with kq = k<=128 ? k : 256-k and sign flip
   (m>512) ^ (k>128) -- arithmetically identical to the scatter version. */
__global__ __launch_bounds__(256)
void comb_ln(const float* __restrict__ sc, const float* __restrict__ bi)
{
    int warp = threadIdx.x >> 5, lane = threadIdx.x & 31;
    size_t row = (size_t)blockIdx.x * 8 + warp;
    if (row >= ROWS) return;
    int b = (int)(row / NTOK), m = (int)(row - (size_t)b * NTOK);
    int mp = (m <= 512) ? m : (NTOK - m);
    bool hi = (m > 512);
    const float* ycr = g_ycq + ((size_t)b * NTOKH + mp) * 136;
    const float* ysr = g_ysq + ((size_t)b * 512 + (mp - 1)) * 128;
    float4* trow = (float4*)(g_t + row * Dd);
    float4 v0 = trow[lane], v1 = trow[lane + 32];
    float tv[8] = { v0.x, v0.y, v0.z, v0.w, v1.x, v1.y, v1.z, v1.w };
#pragma unroll
    for (int i = 0; i < 8; i++) {
        int k = (i < 4) ? (4 * lane + i) : (128 + 4 * lane + (i - 4));
        int kq = (k <= 128) ? k : (256 - k);
        float yc = ycr[kq];
        float ys = 0.f;
        if (mp >= 1 && kq >= 1 && kq <= 127) ys = ysr[kq - 1];
        bool flip = hi ^ (k > 128);
        tv[i] += flip ? (yc + ys) : (yc - ys);
    }
    trow[lane]      = make_float4(tv[0], tv[1], tv[2], tv[3]);
    trow[lane + 32] = make_float4(tv[4], tv[5], tv[6], tv[7]);
    /* LN over updated row */
    float s = tv[0] + tv[1] + tv[2] + tv[3] + tv[4] + tv[5] + tv[6] + tv[7];
#pragma unroll
    for (int o = 16; o; o >>= 1) s += __shfl_xor_sync(0xffffffffu, s, o);
    float mean = s * (1.f / Dd);
    float d0[8];
#pragma unroll
    for (int i = 0; i < 8; i++) d0[i] = tv[i] - mean;
    float q = 0.f;
#pragma unroll
    for (int i = 0; i < 8; i++) q = fmaf(d0[i], d0[i], q);
#pragma unroll
    for (int o = 16; o; o >>= 1) q += __shfl_xor_sync(0xffffffffu, q, o);
    float inv = rsqrtf(q * (1.f / Dd) + EPSV);
    float4 s0 = ((const float4*)sc)[lane], s1 = ((const float4*)sc)[lane + 32];
    float4 b0 = ((const float4*)bi)[lane], b1 = ((const float4*)bi)[lane + 32];
    float scv[8] = { s0.x, s0.y, s0.z, s0.w, s1.x, s1.y, s1.z, s1.w };
    float biv[8] = { b0.x, b0.y, b0.z, b0.w, b1.x, b1.y, b1.z, b1.w };
    u16 hh[8];
#pragma unroll
    for (int i = 0; i < 8; i++) hh[i] = f2b(d0[i] * inv * scv[i] + biv[i]);
    uint2* dh = (uint2*)(g_hh + row * Dd);
    dh[lane]      = *(uint2*)&hh[0];
    dh[lane + 32] = *(uint2*)&hh[4];
}

/* fold tokens: v[r,j] = t1f[r,j] +/- t1f[r,1025-j]; split to bf16 hi/lo */
__global__ void fold_tok()
{
    int j = threadIdx.x;                 /* 0..512 valid (block 544) */
    if (j >= KFOLD) return;
    int r = blockIdx.x, b = blockIdx.y;
    const float* src = g_t1f + ((size_t)b * Dd + r) * NTOKP;
    float v = src[j];
    if (j > 0) {
        float mirr = src[NTOK - j];      /* 1025 - j */
        v = (r < 129) ? v + mirr : v - mirr;
    }
    size_t o = ((size_t)b * Dd + r) * LDV + j;
    split3(v, g_vh[o], g_vl[o]);
}
__global__ void pool_zero()
{
    g_pool[blockIdx.x * 256 + threadIdx.x] = 0.f;
}
__global__ void pool_part()
{
    int b = blockIdx.x, c = blockIdx.y, d = threadIdx.x;
    int p0 = c * 128, p1 = p0 + 128 < NTOK ? p0 + 128 : NTOK;
    float s = 0.f;
    const float* base = g_t + (size_t)b * NTOK * Dd + d;
    for (int p = p0; p < p1; p++) s += base[(size_t)p * Dd];
    atomicAdd(&g_pool[b * Dd + d], s * (1.f / (float)NTOK));
}
__global__ void head_kernel(const float* __restrict__ hs, const float* __restrict__ hbv,
                            const float* __restrict__ W, const float* __restrict__ hbias,
                            float* __restrict__ out)
{
    int b = blockIdx.x, tid = threadIdx.x;
    int lane = tid & 31, wid = tid >> 5;
    __shared__ float row[Dd]; __shared__ float logits[NCls];
    __shared__ float wr[8]; __shared__ float sv;
    float v = g_pool[b * Dd + tid];
    float s = v;
#pragma unroll
    for (int o = 16; o; o >>= 1) s += __shfl_xor_sync(0xffffffffu, s, o);
    if (!lane) wr[wid] = s;
    __syncthreads();
    if (!tid) { float a = 0; for (int i = 0; i < 8; i++) a += wr[i]; sv = a * (1.f / Dd); }
    __syncthreads();
    float m = sv, d = v - m;
    s = d * d;
#pragma unroll
    for (int o = 16; o; o >>= 1) s += __shfl_xor_sync(0xffffffffu, s, o);
    if (!lane) wr[wid] = s;
    __syncthreads();
    if (!tid) { float a = 0; for (int i = 0; i < 8; i++) a += wr[i]; sv = rsqrtf(a * (1.f / Dd) + EPSV); }
    __syncthreads();
    row[tid] = d * sv * hs[tid] + hbv[tid];
    __syncthreads();
    for (int n = tid; n < NCls; n += 256) {
        float acc = hbias[n];
        for (int k = 0; k < Dd; k++) acc = fmaf(row[k], W[(size_t)k * NCls + n], acc);
        logits[n] = acc;
    }
    __syncthreads();
    float mx = -1e30f;
    for (int n = tid; n < NCls; n += 256) mx = fmaxf(mx, logits[n]);
#pragma unroll
    for (int o = 16; o; o >>= 1) mx = fmaxf(mx, __shfl_xor_sync(0xffffffffu, mx, o));
    if (!lane) wr[wid] = mx;
    __syncthreads();
    if (!tid) { float a = -1e30f; for (int i = 0; i < 8; i++) a = fmaxf(a, wr[i]); sv = a; }
    __syncthreads();
    mx = sv;
    float ls = 0.f;
    for (int n = tid; n < NCls; n += 256) { float e = expf(logits[n] - mx); logits[n] = e; ls += e; }
#pragma unroll
    for (int o = 16; o; o >>= 1) ls += __shfl_xor_sync(0xffffffffu, ls, o);
    if (!lane) wr[wid] = ls;
    __syncthreads();
    if (!tid) { float a = 0; for (int i = 0; i < 8; i++) a += wr[i]; sv = 1.f / a; }
    __syncthreads();
    float inv = sv;
    for (int n = tid; n < NCls; n += 256) out[(size_t)b * NCls + n] = logits[n] * inv;
}

/* ---------------- host ---------------- */
template<int EPI>
static void launch_mm(const u16* Ah, const u16* Al, int lda, long long sA,
                      const u16* Bh, const u16* Bl, int ldb, long long sB,
                      int M, int N, int K, const float* bias, const float* pos,
                      float* C, u16* Ch, int ldc, long long sC, int batch, int npass)
{
    dim3 grid((N + 127) / 128, (M + 127) / 128, batch);
    mmg<EPI><<<grid, 256>>>(Ah, Al, lda, sA, Bh, Bl, ldb, sB, M, N, K,
                            bias, pos, C, Ch, ldc, sC, npass);
}

extern "C" void kernel_launch(void* const* d_in, const int* in_sizes, int n_in,
                              void* d_out, int out_size)
{
    (void)in_sizes; (void)n_in; (void)out_size;
    const float* x      = (const float*)d_in[0];
    const float* conv_w = (const float*)d_in[1];
    const float* conv_b = (const float*)d_in[2];
    const float* pos    = (const float*)d_in[3];
    const float* cls    = (const float*)d_in[4];
    const float* ln1s   = (const float*)d_in[5];
    const float* ln1b   = (const float*)d_in[6];
    const float* ln2s   = (const float*)d_in[7];
    const float* ln2b   = (const float*)d_in[8];
    const float* w1     = (const float*)d_in[9];
    const float* b1     = (const float*)d_in[10];
    const float* w2     = (const float*)d_in[11];
    const float* b2     = (const float*)d_in[12];
    const float* hlns   = (const float*)d_in[13];
    const float* hlnb   = (const float*)d_in[14];
    const float* hw     = (const float*)d_in[15];
    const float* hb     = (const float*)d_in[16];
    float* out = (float*)d_out;

    float *t, *t1f, *ycq, *ysq;
    u16 *vh, *vl, *colh, *coll, *hh, *hidh;
    u16 *cmh, *cml, *smh, *sml, *stkh, *stkl, *w1h, *w2h, *cwh;
    cudaGetSymbolAddress((void**)&t,    g_t);
    cudaGetSymbolAddress((void**)&t1f,  g_t1f);
    cudaGetSymbolAddress((void**)&ycq,  g_ycq);  cudaGetSymbolAddress((void**)&ysq,  g_ysq);
    cudaGetSymbolAddress((void**)&vh,   g_vh);   cudaGetSymbolAddress((void**)&vl,   g_vl);
    cudaGetSymbolAddress((void**)&colh, g_colh); cudaGetSymbolAddress((void**)&coll, g_coll);
    cudaGetSymbolAddress((void**)&hh,   g_hh);
    cudaGetSymbolAddress((void**)&hidh, g_hidh);
    cudaGetSymbolAddress((void**)&cmh,  g_cmh);  cudaGetSymbolAddress((void**)&cml,  g_cml);
    cudaGetSymbolAddress((void**)&smh,  g_smh);  cudaGetSymbolAddress((void**)&sml,  g_sml);
    cudaGetSymbolAddress((void**)&stkh, g_stkh); cudaGetSymbolAddress((void**)&stkl, g_stkl);
    cudaGetSymbolAddress((void**)&w1h,  g_w1h);  cudaGetSymbolAddress((void**)&w2h,  g_w2h);
    cudaGetSymbolAddress((void**)&cwh,  g_cwh);

    /* setup: tables + operand conversions (recomputed every call) */
    {
        long long n = (long long)NTOKH * KMP;
        dft_split<<<(unsigned)((n + 255) / 256), 256>>>();
        long long nc = (long long)Bsz * NPp * KIN;
        im2col_split<<<(unsigned)((nc + 255) / 256), 256>>>(x);
        convw_hi<<<(Dd * KIN + 255) / 256, 256>>>(conv_w);
        w12t_hi<<<(NL * Dd * HIDN + 255) / 256, 256>>>(w1, w2);
    }

    /* patch embed (2-pass): col @ convW^T -> g_t rows 1..1024 (+conv_b+pos) */
    launch_mm<6>(colh, coll, KIN, (long long)NPp * KIN,
                 cwh, nullptr, KIN, 0,
                 NPp, Dd, KIN, conv_b, pos,
                 t + Dd, nullptr, Dd, (long long)NTOK * Dd, Bsz, 2);
    cls_row<<<Bsz, Dd>>>(pos, cls);

    const long long sBT  = (long long)NTOK * Dd;     /* h per-batch stride        */
    const long long sT1F = (long long)Dd * NTOKP;    /* t1f per-batch stride      */
    const long long sV   = (long long)Dd * LDV;      /* folded v per-batch stride */
    const long long sYC  = (long long)NTOKH * 136;   /* Ycq per-batch stride      */
    const long long sYS  = (long long)512 * 128;     /* Ysq per-batch stride      */

    for (int i = 0; i < NL; i++) {
        /* ---- token mixing: stage-1 2-pass (table hi+lo x h hi), stage-2 3-pass ---- */
        ln_split<<<(ROWS + 7) / 8, 256>>>(ln1s + i * Dd, ln1b + i * Dd);
        /* stage 1: t1f(256 x 1025, fp32) = [CN0..128; SN1..127] @ h^T, per batch */
        launch_mm<5>(stkh, stkl, Dd, 0, hh, nullptr, Dd, sBT,
                     Dd, NTOK, Dd, nullptr, nullptr,
                     t1f, nullptr, NTOKP, sT1F, Bsz, 2);
        /* token fold: v[r,j] = t1f[r,j] +/- t1f[r,1025-j], split to bf16 hi/lo */
        fold_tok<<<dim3(Dd, Bsz), 544>>>();
        /* stage 2 fused cos+sin+boundary: y<4 cos, 4<=y<8 sin, y>=8 bound */
        mmg_dual<<<dim3(1, 89, Bsz), 256>>>(
            cmh, cml, vh, vl, ycq, 136, sYC,
            smh + KMP, sml + KMP,
            vh + (size_t)129 * LDV, vl + (size_t)129 * LDV, ysq, 128, sYS,
            sV);
        /* fused combine + ln2 -> updates g_t, writes hh */
        comb_ln<<<(ROWS + 7) / 8, 256>>>(ln2s + i * Dd, ln2b + i * Dd);

        /* ---- FFN (1-pass: data hi x weight hi) ---- */
        launch_mm<1>(hh, hh, Dd, 0,
                     w1h + (size_t)i * Dd * HIDN, nullptr, Dd, 0,
                     ROWS, HIDN, Dd, b1 + i * HIDN, nullptr,
                     nullptr, hidh, HIDN, 0, 1, 1);
        launch_mm<3>(hidh, hidh, HIDN, 0,
                     w2h + (size_t)i * Dd * HIDN, nullptr, HIDN, 0,
                     ROWS, Dd, HIDN, b2 + i * Dd, nullptr,
                     t, nullptr, Dd, 0, 1, 1);
    }

    pool_zero<<<Bsz, Dd>>>();
    pool_part<<<dim3(Bsz, 9), Dd>>>();
    head_kernel<<<Bsz, Dd>>>(hlns, hlnb, hw, hb, out);
}

// round 16
// speedup vs baseline: 1.0873x; 1.0873x over previous
#include <cuda_runtime.h>
#include <cuda_bf16.h>
#include <stdint.h>
#include <math.h>

typedef unsigned short u16;
typedef unsigned int   u32;
typedef unsigned long long u64;

#define Bsz  64
#define Dd   256
#define NPp  1024
#define NTOK 1025
#define NTOKP 1032         /* 1025 padded to mult of 8 -> 16B-aligned rows */
#define NTOKH 513          /* quadrant rows 0..512 */
#define KFOLD 513          /* folded token-K */
#define LDV  520           /* 513 padded to mult of 8 */
#define HIDN 1024
#define NL   6
#define NCls 1000
#define ROWS 65600
#define KIN  768
#define KMP  1088          /* 1025 padded to mult of 64 */
#define EPSV 1e-5f

/* ---------------- device-global scratch ---------------- */
__device__ float g_t   [(size_t)ROWS*Dd];
__device__ float g_pool[Bsz*Dd];
__device__ float g_t1f [(size_t)Bsz*Dd*NTOKP];    /* stage-1 fp32 out (u1;u2) */
__device__ float g_ycq [(size_t)Bsz*NTOKH*136];   /* cos quadrant (ld 136) */
__device__ float g_ysq [(size_t)Bsz*512*128];     /* sin quadrant 512x127 (ld 128) */
__device__ __align__(16) u16 g_vh  [(size_t)Bsz*Dd*LDV];   /* folded stage-2 B, hi */
__device__ __align__(16) u16 g_vl  [(size_t)Bsz*Dd*LDV];   /* folded stage-2 B, lo */
__device__ __align__(16) u16 g_colh[(size_t)Bsz*NPp*KIN];
__device__ __align__(16) u16 g_coll[(size_t)Bsz*NPp*KIN];
__device__ __align__(16) u16 g_hh  [(size_t)ROWS*Dd];
__device__ __align__(16) u16 g_hidh[(size_t)ROWS*HIDN];
__device__ __align__(16) u16 g_cmh [(size_t)NTOKH*KMP];
__device__ __align__(16) u16 g_cml [(size_t)NTOKH*KMP];
__device__ __align__(16) u16 g_smh [(size_t)NTOKH*KMP];
__device__ __align__(16) u16 g_sml [(size_t)NTOKH*KMP];
__device__ __align__(16) u16 g_stkh[Dd*Dd], g_stkl[Dd*Dd];  /* stacked [CN0..128;SN1..127] */
__device__ __align__(16) u16 g_w1h [NL*Dd*HIDN];
__device__ __align__(16) u16 g_w2h [NL*Dd*HIDN];
__device__ __align__(16) u16 g_cwh [Dd*KIN];

/* ---------------- helpers ---------------- */
__device__ __forceinline__ u32 s2u(const void* p){
    u32 a; asm("{ .reg .u64 t; cvta.to.shared.u64 t, %1; cvt.u32.u64 %0, t; }" : "=r"(a) : "l"(p));
    return a;
}
__device__ __forceinline__ void split3(float v, u16& hu, u16& lu){
    __nv_bfloat16 h = __float2bfloat16(v);
    hu = __bfloat16_as_ushort(h);
    lu = __bfloat16_as_ushort(__float2bfloat16(v - __bfloat162float(h)));
}
__device__ __forceinline__ float b2f(u16 u){
    return __bfloat162float(__ushort_as_bfloat16(u));
}
__device__ __forceinline__ u16 f2b(float v){
    return __bfloat16_as_ushort(__float2bfloat16(v));
}

#define CPA(s, g, n) asm volatile("cp.async.ca.shared.global [%0], [%1], 16, %2;" :: "r"(s), "l"(g), "r"(n) : "memory")
#define CP_COMMIT()  asm volatile("cp.async.commit_group;" ::: "memory")

#define LDSM4(r, a) asm volatile("ldmatrix.sync.aligned.m8n8.x4.shared.b16 {%0,%1,%2,%3}, [%4];" \
    : "=r"((r)[0]), "=r"((r)[1]), "=r"((r)[2]), "=r"((r)[3]) : "r"(a))

#define MMA16816(d, a, b0v, b1v)                                               \
    asm volatile("mma.sync.aligned.m16n8k16.row.col.f32.bf16.bf16.f32 "        \
        "{%0,%1,%2,%3},{%4,%5,%6,%7},{%8,%9},{%0,%1,%2,%3};"                   \
        : "+f"((d)[0]), "+f"((d)[1]), "+f"((d)[2]), "+f"((d)[3])               \
        : "r"((a)[0]), "r"((a)[1]), "r"((a)[2]), "r"((a)[3]), "r"(b0v), "r"(b1v))

/* ---------------- stage one 128x32 A-tile + 128x32 B-tile into smem -------- */
__device__ __forceinline__ void stage_tile(u32 sa, u32 sbm,
    const u16* __restrict__ As, const u16* __restrict__ Bs,
    int lda, int ldb, int M, int N, int K, int m0, int n0, int k0, int tid)
{
#pragma unroll
    for (int i = 0; i < 2; i++) {
        int slot = tid + i * 256;
        int r = slot >> 2, c = slot & 3;
        int kk = k0 + c * 8;
        int gm = m0 + r;
        int bytes = 0; size_t off = 0;
        if (gm < M && kk < K) { bytes = (K - kk >= 8) ? 16 : (K - kk) * 2; off = (size_t)gm * lda + kk; }
        CPA(sa + r * 80 + c * 16, As + off, bytes);
    }
#pragma unroll
    for (int i = 0; i < 2; i++) {
        int slot = tid + i * 256;
        int r = slot >> 2, c = slot & 3;
        int kk = k0 + c * 8;
        int gn = n0 + r;
        int bytes = 0; size_t off = 0;
        if (gn < N && kk < K) { bytes = (K - kk >= 8) ? 16 : (K - kk) * 2; off = (size_t)gn * ldb + kk; }
        CPA(sbm + r * 80 + c * 16, Bs + off, bytes);
    }
    CP_COMMIT();
}

/* ---------------- shared GEMM body: D(tile at m0,n0) = A @ B^T, bf16 split --
   npass=3: Ah.Bh + Al.Bh + Ah.Bl ; npass=2: Ah.Bh + Al.Bh ; npass=1: Ah.Bh
   EPI: 1 bias+leaky+hi-store   3 f32 C += acc + bias
        5 f32 C = acc           6 f32 C = acc + bias + pos(row gm+1) */
template<int EPI>
__device__ __forceinline__ void mm_body(
    u32 sa0, u32 sa1, u32 sb0, u32 sb1,
    const u16* __restrict__ Ah, const u16* __restrict__ Al, int lda,
    const u16* __restrict__ Bh, const u16* __restrict__ Bl, int ldb,
    int M, int N, int K, int m0, int n0,
    const float* __restrict__ bias, const float* __restrict__ pos,
    float* C, u16* Ch, int ldc, int npass)
{
    const int tid = threadIdx.x, lane = tid & 31, wid = tid >> 5;
    const int wm = wid & 3, wn = wid >> 2;

    const u16* Ap[3] = { Ah, Al, Ah };
    const u16* Bp[3] = { Bh, Bh, Bl };
    const int nk = (K + 31) >> 5, total = npass * nk;

    float acc[2][8][4];
#pragma unroll
    for (int mi = 0; mi < 2; mi++)
#pragma unroll
        for (int n8 = 0; n8 < 8; n8++)
#pragma unroll
            for (int q = 0; q < 4; q++) acc[mi][n8][q] = 0.f;

    stage_tile(sa0, sb0, Ap[0], Bp[0], lda, ldb, M, N, K, m0, n0, 0, tid);

    for (int it = 0; it < total; it++) {
        if (it + 1 < total) {
            int p = (it + 1) / nk, kc = (it + 1) - p * nk;
            stage_tile(((it + 1) & 1) ? sa1 : sa0, ((it + 1) & 1) ? sb1 : sb0,
                       Ap[p], Bp[p], lda, ldb, M, N, K, m0, n0, kc * 32, tid);
            asm volatile("cp.async.wait_group 1;" ::: "memory");
        } else {
            asm volatile("cp.async.wait_group 0;" ::: "memory");
        }
        __syncthreads();
        u32 sa = (it & 1) ? sa1 : sa0, smb = (it & 1) ? sb1 : sb0;
#pragma unroll
        for (int kk = 0; kk < 32; kk += 16) {
            u32 a[2][4], b[4][4];
#pragma unroll
            for (int mi = 0; mi < 2; mi++)
                LDSM4(a[mi], sa + (u32)((wm * 32 + mi * 16 + (lane & 15)) * 80
                                        + (kk + (lane >> 4) * 8) * 2));
#pragma unroll
            for (int nj = 0; nj < 4; nj++)
                LDSM4(b[nj], smb + (u32)((wn * 64 + nj * 16 + ((lane >> 4) << 3) + (lane & 7)) * 80
                                         + (kk + ((lane >> 3) & 1) * 8) * 2));
#pragma unroll
            for (int mi = 0; mi < 2; mi++)
#pragma unroll
                for (int n8 = 0; n8 < 8; n8++)
                    MMA16816(acc[mi][n8], a[mi], b[n8 >> 1][(n8 & 1) * 2], b[n8 >> 1][(n8 & 1) * 2 + 1]);
        }
        __syncthreads();
    }

    /* epilogue from register fragments */
#pragma unroll
    for (int mi = 0; mi < 2; mi++) {
        int rbase = m0 + wm * 32 + mi * 16 + (lane >> 2);
#pragma unroll
        for (int half = 0; half < 2; half++) {
            int gm = rbase + half * 8;
            if (gm >= M) continue;
#pragma unroll
            for (int n8 = 0; n8 < 8; n8++) {
                int gn = n0 + wn * 64 + n8 * 8 + (lane & 3) * 2;
                if (gn >= N) continue;
                float v0 = acc[mi][n8][half * 2], v1 = acc[mi][n8][half * 2 + 1];
                size_t off = (size_t)gm * ldc + gn;
                if (EPI == 1) {
                    v0 += bias[gn];     v0 = v0 > 0.f ? v0 : 0.01f * v0;
                    v1 += bias[gn + 1]; v1 = v1 > 0.f ? v1 : 0.01f * v1;
                    u32 hp = (u32)f2b(v0) | ((u32)f2b(v1) << 16);
                    *(u32*)(Ch + off) = hp;
                } else if (EPI == 5) {
                    *(float2*)(C + off) = make_float2(v0, v1);
                } else if (EPI == 6) {
                    size_t po = (size_t)(gm + 1) * Dd + gn;
                    *(float2*)(C + off) = make_float2(v0 + bias[gn] + pos[po],
                                                      v1 + bias[gn + 1] + pos[po + 1]);
                } else {            /* EPI == 3 */
                    float2 c = *(const float2*)(C + off);
                    c.x += v0 + bias[gn];
                    c.y += v1 + bias[gn + 1];
                    *(float2*)(C + off) = c;
                }
            }
        }
    }
}

/* ---------------- generic single GEMM kernel ---------------- */
template<int EPI>
__global__ __launch_bounds__(256, 2)
void mmg(const u16* __restrict__ Ah, const u16* __restrict__ Al, int lda, long long sA,
         const u16* __restrict__ Bh, const u16* __restrict__ Bl, int ldb, long long sB,
         int M, int N, int K, const float* __restrict__ bias, const float* __restrict__ pos,
         float* C, u16* Ch, int ldc, long long sC, int npass)
{
    __shared__ __align__(16) u16 SA[2][128][40];
    __shared__ __align__(16) u16 SB[2][128][40];
    const int bz = blockIdx.z;
    Ah += bz * sA; Al += bz * sA; Bh += bz * sB;
    if (Bl) Bl += bz * sB;
    if (C)  C  += bz * sC;
    if (Ch) Ch += bz * sC;
    mm_body<EPI>(s2u(&SA[0][0][0]), s2u(&SA[1][0][0]),
                 s2u(&SB[0][0][0]), s2u(&SB[1][0][0]),
                 Ah, Al, lda, Bh, Bl, ldb, M, N, K,
                 blockIdx.y * 128, blockIdx.x * 128, bias, pos, C, Ch, ldc, npass);
}

/* ---------------- dual GEMM kernel: stage-2 cos (y<4) + sin (y>=4) --------- */
__global__ __launch_bounds__(256, 2)
void mmg_dual(const u16* __restrict__ A0h, const u16* __restrict__ A0l,
              const u16* __restrict__ B0h, const u16* __restrict__ B0l,
              float* C0, int ldc0, long long sC0,
              const u16* __restrict__ A1h, const u16* __restrict__ A1l,
              const u16* __restrict__ B1h, const u16* __restrict__ B1l,
              float* C1, int ldc1, long long sC1,
              long long sB)
{
    __shared__ __align__(16) u16 SA[2][128][40];
    __shared__ __align__(16) u16 SB[2][128][40];
    const int bz = blockIdx.z;
    const int sel = blockIdx.y >= 4;
    const u16 *Ah, *Al, *Bh, *Bl;
    float* C; int ldc, N, m0;
    if (!sel) {
        Ah = A0h; Al = A0l;
        Bh = B0h + bz * sB; Bl = B0l + bz * sB;
        C = C0 + bz * sC0; ldc = ldc0; N = 128;
        m0 = blockIdx.y * 128;
    } else {
        Ah = A1h; Al = A1l;
        Bh = B1h + bz * sB; Bl = B1l + bz * sB;
        C = C1 + bz * sC1; ldc = ldc1; N = 127;
        m0 = (blockIdx.y - 4) * 128;
    }
    mm_body<5>(s2u(&SA[0][0][0]), s2u(&SA[1][0][0]),
               s2u(&SB[0][0][0]), s2u(&SB[1][0][0]),
               Ah, Al, KMP, Bh, Bl, LDV, 512, N, KFOLD,
               m0, 0, nullptr, nullptr, C, nullptr, ldc, 3);
}

/* ---------------- tables ---------------- */
__global__ void dft_split()
{
    long long idx = (long long)blockIdx.x * blockDim.x + threadIdx.x;
    const float TP = 6.283185307179586f;
    if (idx < (long long)NTOKH * KMP) {      /* quadrant rows 0..512 of CM/SM */
        int m = (int)(idx / KMP), j = (int)(idx % KMP);
        float c = 0.f, s = 0.f;
        if (j < NTOK) {
            int r = (int)(((long long)m * j) % NTOK);
            float a = (float)r * (TP / (float)NTOK);
            sincosf(a, &s, &c);
        }
        split3(c, g_cmh[idx], g_cml[idx]);
        split3(s, g_smh[idx], g_sml[idx]);
    }
    if (idx < Dd * Dd) {                     /* stacked dim table */
        int r = (int)(idx >> 8), d = (int)(idx & 255);
        float v;
        if (r < 129) {
            int rr = (r * d) & 255;
            v = cosf((float)rr * (TP / 256.f));
        } else {
            int rr = ((r - 128) * d) & 255;
            v = sinf((float)rr * (TP / 256.f));
        }
        split3(v, g_stkh[idx], g_stkl[idx]);
    }
}
__global__ void im2col_split(const float* __restrict__ x)
{
    long long idx = (long long)blockIdx.x * blockDim.x + threadIdx.x;
    if (idx >= (long long)Bsz * NPp * KIN) return;
    int k = (int)(idx % KIN);
    long long rp = idx / KIN;
    int p = (int)(rp % NPp), b = (int)(rp / NPp);
    int c = k >> 8, py = (k >> 4) & 15, px = k & 15;
    int gh = p >> 5, gw = p & 31;
    float v = x[(((size_t)b * 3 + c) * 512 + gh * 16 + py) * 512 + gw * 16 + px];
    split3(v, g_colh[idx], g_coll[idx]);
}
__global__ void convw_hi(const float* __restrict__ cw)
{
    int idx = blockIdx.x * blockDim.x + threadIdx.x;
    if (idx < Dd * KIN) g_cwh[idx] = f2b(cw[idx]);
}
__global__ void w12t_hi(const float* __restrict__ w1, const float* __restrict__ w2)
{
    int idx = blockIdx.x * blockDim.x + threadIdx.x;
    if (idx >= NL * Dd * HIDN) return;
    int l = idx / (Dd * HIDN), r = idx % (Dd * HIDN);
    int n1 = r / Dd, k1 = r % Dd;
    g_w1h[idx] = f2b(w1[(size_t)l * Dd * HIDN + (size_t)k1 * HIDN + n1]);
    int n2 = r / HIDN, k2 = r % HIDN;
    g_w2h[idx] = f2b(w2[(size_t)l * Dd * HIDN + (size_t)k2 * Dd + n2]);
}
/* cls row: t[b,0,:] = cls + pos[0,:] */
__global__ void cls_row(const float* __restrict__ pos, const float* __restrict__ cls)
{
    int d = threadIdx.x, b = blockIdx.x;
    g_t[(size_t)b * NTOK * Dd + d] = cls[d] + pos[d];
}

/* warp-per-row LN -> bf16 hi only; 8 rows per block, no __syncthreads */
__global__ __launch_bounds__(256)
void ln_split(const float* __restrict__ sc, const float* __restrict__ bi)
{
    int warp = threadIdx.x >> 5, lane = threadIdx.x & 31;
    size_t row = (size_t)blockIdx.x * 8 + warp;
    if (row >= ROWS) return;
    const float4* src = (const float4*)(g_t + row * Dd);
    float4 v0 = src[lane], v1 = src[lane + 32];
    float s = v0.x + v0.y + v0.z + v0.w + v1.x + v1.y + v1.z + v1.w;
#pragma unroll
    for (int o = 16; o; o >>= 1) s += __shfl_xor_sync(0xffffffffu, s, o);
    float m = s * (1.f / Dd);
    float d0[8] = { v0.x - m, v0.y - m, v0.z - m, v0.w - m,
                    v1.x - m, v1.y - m, v1.z - m, v1.w - m };
    float q = 0.f;
#pragma unroll
    for (int i = 0; i < 8; i++) q = fmaf(d0[i], d0[i], q);
#pragma unroll
    for (int o = 16; o; o >>= 1) q += __shfl_xor_sync(0xffffffffu, q, o);
    float inv = rsqrtf(q * (1.f / Dd) + EPSV);
    float4 s0 = ((const float4*)sc)[lane], s1 = ((const float4*)sc)[lane + 32];
    float4 b0 = ((const float4*)bi)[lane], b1 = ((const float4*)bi)[lane + 32];
    float scv[8] = { s0.x, s0.y, s0.z, s0.w, s1.x, s1.y, s1.z, s1.w };
    float biv[8] = { b0.x, b0.y, b0.z, b0.w, b1.x, b1.y, b1.z, b1.w };
    u16 hh[8];
#pragma unroll
    for (int i = 0; i < 8; i++) hh[i] = f2b(d0[i] * inv * scv[i] + biv[i]);
    uint2* dh = (uint2*)(g_hh + row * Dd);
    dh[lane]      = *(uint2*)&hh[0];
    dh[lane + 32] = *(uint2*)&hh[4];
}

/* fused combine_quad + ln2: warp per token row (arithmetically identical to
   the scatter combine + separate ln). */
__global__ __launch_bounds__(256)
void comb_ln(const float* __restrict__ sc, const float* __restrict__ bi)
{
    int warp = threadIdx.x >> 5, lane = threadIdx.x & 31;
    size_t row = (size_t)blockIdx.x * 8 + warp;
    if (row >= ROWS) return;
    int b = (int)(row / NTOK), m = (int)(row - (size_t)b * NTOK);
    int mp = (m <= 512) ? m : (NTOK - m);
    bool hi = (m > 512);
    const float* ycr = g_ycq + ((size_t)b * NTOKH + mp) * 136;
    const float* ysr = g_ysq + ((size_t)b * 512 + (mp - 1)) * 128;
    float4* trow = (float4*)(g_t + row * Dd);
    float4 v0 = trow[lane], v1 = trow[lane + 32];
    float tv[8] = { v0.x, v0.y, v0.z, v0.w, v1.x, v1.y, v1.z, v1.w };
#pragma unroll
    for (int i = 0; i < 8; i++) {
        int k = (i < 4) ? (4 * lane + i) : (128 + 4 * lane + (i - 4));
        int kq = (k <= 128) ? k : (256 - k);
        float yc = ycr[kq];
        float ys = 0.f;
        if (mp >= 1 && kq >= 1 && kq <= 127) ys = ysr[kq - 1];
        bool flip = hi ^ (k > 128);
        tv[i] += flip ? (yc + ys) : (yc - ys);
    }
    trow[lane]      = make_float4(tv[0], tv[1], tv[2], tv[3]);
    trow[lane + 32] = make_float4(tv[4], tv[5], tv[6], tv[7]);
    /* LN over updated row */
    float s = tv[0] + tv[1] + tv[2] + tv[3] + tv[4] + tv[5] + tv[6] + tv[7];
#pragma unroll
    for (int o = 16; o; o >>= 1) s += __shfl_xor_sync(0xffffffffu, s, o);
    float mean = s * (1.f / Dd);
    float d0[8];
#pragma unroll
    for (int i = 0; i < 8; i++) d0[i] = tv[i] - mean;
    float q = 0.f;
#pragma unroll
    for (int i = 0; i < 8; i++) q = fmaf(d0[i], d0[i], q);
#pragma unroll
    for (int o = 16; o; o >>= 1) q += __shfl_xor_sync(0xffffffffu, q, o);
    float inv = rsqrtf(q * (1.f / Dd) + EPSV);
    float4 s0 = ((const float4*)sc)[lane], s1 = ((const float4*)sc)[lane + 32];
    float4 b0 = ((const float4*)bi)[lane], b1 = ((const float4*)bi)[lane + 32];
    float scv[8] = { s0.x, s0.y, s0.z, s0.w, s1.x, s1.y, s1.z, s1.w };
    float biv[8] = { b0.x, b0.y, b0.z, b0.w, b1.x, b1.y, b1.z, b1.w };
    u16 hh[8];
#pragma unroll
    for (int i = 0; i < 8; i++) hh[i] = f2b(d0[i] * inv * scv[i] + biv[i]);
    uint2* dh = (uint2*)(g_hh + row * Dd);
    dh[lane]      = *(uint2*)&hh[0];
    dh[lane + 32] = *(uint2*)&hh[4];
}

/* fold tokens: v[r,j] = t1f[r,j] +/- t1f[r,1025-j]; split to bf16 hi/lo */
__global__ void fold_tok()
{
    int j = threadIdx.x;                 /* 0..512 valid (block 544) */
    if (j >= KFOLD) return;
    int r = blockIdx.x, b = blockIdx.y;
    const float* src = g_t1f + ((size_t)b * Dd + r) * NTOKP;
    float v = src[j];
    if (j > 0) {
        float mirr = src[NTOK - j];      /* 1025 - j */
        v = (r < 129) ? v + mirr : v - mirr;
    }
    size_t o = ((size_t)b * Dd + r) * LDV + j;
    split3(v, g_vh[o], g_vl[o]);
}

/* boundary GEMV: fill ycq row m=512 (k=0..128) and column k=128 (m=0..511).
   641 dots of length 513 per batch; warp per dot; fp32 via hi+lo reconstruction. */
__global__ __launch_bounds__(256)
void bound_gemv()
{
    int gw = (blockIdx.x * 256 + threadIdx.x) >> 5;
    int lane = threadIdx.x & 31;
    int b = blockIdx.y;
    if (gw >= 641) return;
    int m, k;
    if (gw < 512) { m = gw; k = 128; }
    else          { m = 512; k = gw - 512; }
    const u16* cmh = g_cmh + (size_t)m * KMP;
    const u16* cml = g_cml + (size_t)m * KMP;
    const u16* vh  = g_vh + ((size_t)b * Dd + k) * LDV;
    const u16* vl  = g_vl + ((size_t)b * Dd + k) * LDV;
    float s = 0.f;
    for (int j = lane; j < KFOLD; j += 32) {
        float cm = b2f(cmh[j]) + b2f(cml[j]);
        float vv = b2f(vh[j])  + b2f(vl[j]);
        s = fmaf(cm, vv, s);
    }
#pragma unroll
    for (int o = 16; o; o >>= 1) s += __shfl_xor_sync(0xffffffffu, s, o);
    if (!lane) g_ycq[((size_t)b * NTOKH + m) * 136 + k] = s;
}
__global__ void pool_zero()
{
    g_pool[blockIdx.x * 256 + threadIdx.x] = 0.f;
}
__global__ void pool_part()
{
    int b = blockIdx.x, c = blockIdx.y, d = threadIdx.x;
    int p0 = c * 128, p1 = p0 + 128 < NTOK ? p0 + 128 : NTOK;
    float s = 0.f;
    const float* base = g_t + (size_t)b * NTOK * Dd + d;
    for (int p = p0; p < p1; p++) s += base[(size_t)p * Dd];
    atomicAdd(&g_pool[b * Dd + d], s * (1.f / (float)NTOK));
}
__global__ void head_kernel(const float* __restrict__ hs, const float* __restrict__ hbv,
                            const float* __restrict__ W, const float* __restrict__ hbias,
                            float* __restrict__ out)
{
    int b = blockIdx.x, tid = threadIdx.x;
    int lane = tid & 31, wid = tid >> 5;
    __shared__ float row[Dd]; __shared__ float logits[NCls];
    __shared__ float wr[8]; __shared__ float sv;
    float v = g_pool[b * Dd + tid];
    float s = v;
#pragma unroll
    for (int o = 16; o; o >>= 1) s += __shfl_xor_sync(0xffffffffu, s, o);
    if (!lane) wr[wid] = s;
    __syncthreads();
    if (!tid) { float a = 0; for (int i = 0; i < 8; i++) a += wr[i]; sv = a * (1.f / Dd); }
    __syncthreads();
    float m = sv, d = v - m;
    s = d * d;
#pragma unroll
    for (int o = 16; o; o >>= 1) s += __shfl_xor_sync(0xffffffffu, s, o);
    if (!lane) wr[wid] = s;
    __syncthreads();
    if (!tid) { float a = 0; for (int i = 0; i < 8; i++) a += wr[i]; sv = rsqrtf(a * (1.f / Dd) + EPSV); }
    __syncthreads();
    row[tid] = d * sv * hs[tid] + hbv[tid];
    __syncthreads();
    for (int n = tid; n < NCls; n += 256) {
        float acc = hbias[n];
        for (int k = 0; k < Dd; k++) acc = fmaf(row[k], W[(size_t)k * NCls + n], acc);
        logits[n] = acc;
    }
    __syncthreads();
    float mx = -1e30f;
    for (int n = tid; n < NCls; n += 256) mx = fmaxf(mx, logits[n]);
#pragma unroll
    for (int o = 16; o; o >>= 1) mx = fmaxf(mx, __shfl_xor_sync(0xffffffffu, mx, o));
    if (!lane) wr[wid] = mx;
    __syncthreads();
    if (!tid) { float a = -1e30f; for (int i = 0; i < 8; i++) a = fmaxf(a, wr[i]); sv = a; }
    __syncthreads();
    mx = sv;
    float ls = 0.f;
    for (int n = tid; n < NCls; n += 256) { float e = expf(logits[n] - mx); logits[n] = e; ls += e; }
#pragma unroll
    for (int o = 16; o; o >>= 1) ls += __shfl_xor_sync(0xffffffffu, ls, o);
    if (!lane) wr[wid] = ls;
    __syncthreads();
    if (!tid) { float a = 0; for (int i = 0; i < 8; i++) a += wr[i]; sv = 1.f / a; }
    __syncthreads();
    float inv = sv;
    for (int n = tid; n < NCls; n += 256) out[(size_t)b * NCls + n] = logits[n] * inv;
}

/* ---------------- host ---------------- */
template<int EPI>
static void launch_mm(const u16* Ah, const u16* Al, int lda, long long sA,
                      const u16* Bh, const u16* Bl, int ldb, long long sB,
                      int M, int N, int K, const float* bias, const float* pos,
                      float* C, u16* Ch, int ldc, long long sC, int batch, int npass)
{
    dim3 grid((N + 127) / 128, (M + 127) / 128, batch);
    mmg<EPI><<<grid, 256>>>(Ah, Al, lda, sA, Bh, Bl, ldb, sB, M, N, K,
                            bias, pos, C, Ch, ldc, sC, npass);
}

extern "C" void kernel_launch(void* const* d_in, const int* in_sizes, int n_in,
                              void* d_out, int out_size)
{
    (void)in_sizes; (void)n_in; (void)out_size;
    const float* x      = (const float*)d_in[0];
    const float* conv_w = (const float*)d_in[1];
    const float* conv_b = (const float*)d_in[2];
    const float* pos    = (const float*)d_in[3];
    const float* cls    = (const float*)d_in[4];
    const float* ln1s   = (const float*)d_in[5];
    const float* ln1b   = (const float*)d_in[6];
    const float* ln2s   = (const float*)d_in[7];
    const float* ln2b   = (const float*)d_in[8];
    const float* w1     = (const float*)d_in[9];
    const float* b1     = (const float*)d_in[10];
    const float* w2     = (const float*)d_in[11];
    const float* b2     = (const float*)d_in[12];
    const float* hlns   = (const float*)d_in[13];
    const float* hlnb   = (const float*)d_in[14];
    const float* hw     = (const float*)d_in[15];
    const float* hb     = (const float*)d_in[16];
    float* out = (float*)d_out;

    float *t, *t1f, *ycq, *ysq;
    u16 *vh, *vl, *colh, *coll, *hh, *hidh;
    u16 *cmh, *cml, *smh, *sml, *stkh, *stkl, *w1h, *w2h, *cwh;
    cudaGetSymbolAddress((void**)&t,    g_t);
    cudaGetSymbolAddress((void**)&t1f,  g_t1f);
    cudaGetSymbolAddress((void**)&ycq,  g_ycq);  cudaGetSymbolAddress((void**)&ysq,  g_ysq);
    cudaGetSymbolAddress((void**)&vh,   g_vh);   cudaGetSymbolAddress((void**)&vl,   g_vl);
    cudaGetSymbolAddress((void**)&colh, g_colh); cudaGetSymbolAddress((void**)&coll, g_coll);
    cudaGetSymbolAddress((void**)&hh,   g_hh);
    cudaGetSymbolAddress((void**)&hidh, g_hidh);
    cudaGetSymbolAddress((void**)&cmh,  g_cmh);  cudaGetSymbolAddress((void**)&cml,  g_cml);
    cudaGetSymbolAddress((void**)&smh,  g_smh);  cudaGetSymbolAddress((void**)&sml,  g_sml);
    cudaGetSymbolAddress((void**)&stkh, g_stkh); cudaGetSymbolAddress((void**)&stkl, g_stkl);
    cudaGetSymbolAddress((void**)&w1h,  g_w1h);  cudaGetSymbolAddress((void**)&w2h,  g_w2h);
    cudaGetSymbolAddress((void**)&cwh,  g_cwh);

    /* setup: tables + operand conversions (recomputed every call) */
    {
        long long n = (long long)NTOKH * KMP;
        dft_split<<<(unsigned)((n + 255) / 256), 256>>>();
        long long nc = (long long)Bsz * NPp * KIN;
        im2col_split<<<(unsigned)((nc + 255) / 256), 256>>>(x);
        convw_hi<<<(Dd * KIN + 255) / 256, 256>>>(conv_w);
        w12t_hi<<<(NL * Dd * HIDN + 255) / 256, 256>>>(w1, w2);
    }

    /* patch embed (2-pass): col @ convW^T -> g_t rows 1..1024 (+conv_b+pos) */
    launch_mm<6>(colh, coll, KIN, (long long)NPp * KIN,
                 cwh, nullptr, KIN, 0,
                 NPp, Dd, KIN, conv_b, pos,
                 t + Dd, nullptr, Dd, (long long)NTOK * Dd, Bsz, 2);
    cls_row<<<Bsz, Dd>>>(pos, cls);

    const long long sBT  = (long long)NTOK * Dd;     /* h per-batch stride        */
    const long long sT1F = (long long)Dd * NTOKP;    /* t1f per-batch stride      */
    const long long sV   = (long long)Dd * LDV;      /* folded v per-batch stride */
    const long long sYC  = (long long)NTOKH * 136;   /* Ycq per-batch stride      */
    const long long sYS  = (long long)512 * 128;     /* Ysq per-batch stride      */

    for (int i = 0; i < NL; i++) {
        /* ---- token mixing: stage-1 2-pass (table hi+lo x h hi), stage-2 3-pass ---- */
        ln_split<<<(ROWS + 7) / 8, 256>>>(ln1s + i * Dd, ln1b + i * Dd);
        /* stage 1: t1f(256 x 1025, fp32) = [CN0..128; SN1..127] @ h^T, per batch */
        launch_mm<5>(stkh, stkl, Dd, 0, hh, nullptr, Dd, sBT,
                     Dd, NTOK, Dd, nullptr, nullptr,
                     t1f, nullptr, NTOKP, sT1F, Bsz, 2);
        /* token fold: v[r,j] = t1f[r,j] +/- t1f[r,1025-j], split to bf16 hi/lo */
        fold_tok<<<dim3(Dd, Bsz), 544>>>();
        /* stage 2 fused cos+sin: grid (1, 8, 64) */
        mmg_dual<<<dim3(1, 8, Bsz), 256>>>(
            cmh, cml, vh, vl, ycq, 136, sYC,
            smh + KMP, sml + KMP,
            vh + (size_t)129 * LDV, vl + (size_t)129 * LDV, ysq, 128, sYS,
            sV);
        /* boundary: ycq row m=512 + column k=128 via warp-dot GEMV */
        bound_gemv<<<dim3(81, Bsz), 256>>>();
        /* fused combine + ln2 -> updates g_t, writes hh */
        comb_ln<<<(ROWS + 7) / 8, 256>>>(ln2s + i * Dd, ln2b + i * Dd);

        /* ---- FFN (1-pass: data hi x weight hi) ---- */
        launch_mm<1>(hh, hh, Dd, 0,
                     w1h + (size_t)i * Dd * HIDN, nullptr, Dd, 0,
                     ROWS, HIDN, Dd, b1 + i * HIDN, nullptr,
                     nullptr, hidh, HIDN, 0, 1, 1);
        launch_mm<3>(hidh, hidh, HIDN, 0,
                     w2h + (size_t)i * Dd * HIDN, nullptr, HIDN, 0,
                     ROWS, Dd, HIDN, b2 + i * Dd, nullptr,
                     t, nullptr, Dd, 0, 1, 1);
    }

    pool_zero<<<Bsz, Dd>>>();
    pool_part<<<dim3(Bsz, 9), Dd>>>();
    head_kernel<<<Bsz, Dd>>>(hlns, hlnb, hw, hb, out);
}